// round 1
// baseline (speedup 1.0000x reference)
#include <cuda_runtime.h>

#define NN 100000
#define NE 800000

// ---------------- scratch (static __device__ globals; no allocs) ----------------
__device__ __align__(16) float g_msg2[7 * NN * 32];   // 89.6 MB
__device__ __align__(16) float g_msg1[2 * NN * 16];
__device__ __align__(16) float g_msg0[2 * NN * 6];
__device__ __align__(16) float g_cnt [3 * NN];
__device__ __align__(16) float g_h0  [NN * 16];
__device__ __align__(16) float g_h1  [NN * 32];
__device__ __align__(16) float g_Wc0[3 * 6 * 16];
__device__ __align__(16) float g_Wc1[3 * 16 * 32];
__device__ __align__(16) float g_Wc2[8 * 32 * 64];
__device__ __align__(16) float g_bc0[16];
__device__ __align__(16) float g_bc1[32];
__device__ __align__(16) float g_bc2[64];

// ---------------- helpers ----------------
__device__ __forceinline__ void red_add_v4(float* a, float4 v) {
    asm volatile("red.global.add.v4.f32 [%0], {%1,%2,%3,%4};"
                 :: "l"(a), "f"(v.x), "f"(v.y), "f"(v.z), "f"(v.w) : "memory");
}
__device__ __forceinline__ void red_add_v2(float* a, float2 v) {
    asm volatile("red.global.add.v2.f32 [%0], {%1,%2};"
                 :: "l"(a), "f"(v.x), "f"(v.y) : "memory");
}

struct ESet { const int* e[7]; float* cnt[7]; };
struct GSrc { const float* p[8]; const float* cnt[8]; };

// ---------------- zero scratch ----------------
__global__ void k_zero() {
    int tid = blockIdx.x * blockDim.x + threadIdx.x;
    int stride = gridDim.x * blockDim.x;
    float4 z = make_float4(0.f, 0.f, 0.f, 0.f);
    float4* a2 = reinterpret_cast<float4*>(g_msg2);
    for (int i = tid; i < 7 * NN * 32 / 4; i += stride) a2[i] = z;
    float4* a1 = reinterpret_cast<float4*>(g_msg1);
    for (int i = tid; i < 2 * NN * 16 / 4; i += stride) a1[i] = z;
    float4* a0 = reinterpret_cast<float4*>(g_msg0);
    for (int i = tid; i < 2 * NN * 6 / 4; i += stride) a0[i] = z;
    float4* ac = reinterpret_cast<float4*>(g_cnt);
    for (int i = tid; i < 3 * NN / 4; i += stride) ac[i] = z;
}

// ---------------- combine weights (self terms + residual projections folded) ----------------
__global__ void k_prep(const float* __restrict__ W0n, const float* __restrict__ W0r,
                       const float* __restrict__ b0,
                       const float* __restrict__ W1n, const float* __restrict__ W1r,
                       const float* __restrict__ b1,  const float* __restrict__ P1,
                       const float* __restrict__ pb1,
                       const float* __restrict__ W2n, const float* __restrict__ W2r,
                       const float* __restrict__ b2,  const float* __restrict__ P2,
                       const float* __restrict__ pb2) {
    int i = blockIdx.x * blockDim.x + threadIdx.x;
    // layer 0: chunks [W0n[0], W0n[1], W0r[0]+W0r[1]]
    if (i < 192) g_Wc0[i] = W0n[i];
    if (i < 96)  g_Wc0[192 + i] = W0r[i] + W0r[96 + i];
    if (i < 16)  g_bc0[i] = b0[i] + b0[16 + i];
    // layer 1: chunks [W1n[0], W1n[1], W1r[0]+W1r[1]+P1]
    if (i < 1024) g_Wc1[i] = W1n[i];
    if (i < 512)  g_Wc1[1024 + i] = W1r[i] + W1r[512 + i] + P1[i];
    if (i < 32)   g_bc1[i] = b1[i] + b1[32 + i] + pb1[i];
    // layer 2: chunks [W2n[0..6], sum(W2r)+P2]
    if (i < 14336) g_Wc2[i] = W2n[i];
    if (i < 2048) {
        float s = P2[i];
        for (int r = 0; r < 7; r++) s += W2r[r * 2048 + i];
        g_Wc2[14336 + i] = s;
    }
    if (i < 64) {
        float s = pb2[i];
        for (int r = 0; r < 7; r++) s += b2[r * 64 + i];
        g_bc2[i] = s;
    }
}

// ---------------- scatter: D=6 (layer 0, x features) ----------------
__global__ void k_scatter6(ESet es, const float* __restrict__ x, float* __restrict__ msg) {
    int e = blockIdx.x * blockDim.x + threadIdx.x;
    if (e >= NE) return;
    int r = blockIdx.y;
    const int* ei = es.e[r];
    int src = __ldg(ei + e);
    int dst = __ldg(ei + NE + e);
    const float2* xs = reinterpret_cast<const float2*>(x + (size_t)src * 6);
    float2 a = __ldg(xs), b = __ldg(xs + 1), c = __ldg(xs + 2);
    float* m = msg + ((size_t)r * NN + dst) * 6;
    red_add_v2(m,     a);
    red_add_v2(m + 2, b);
    red_add_v2(m + 4, c);
}

// ---------------- scatter: D = 4*NV4 floats per node row ----------------
template <int NV4>
__global__ void k_scatter(ESet es, const float* __restrict__ feat, float* __restrict__ msg) {
    int e = blockIdx.x * blockDim.x + threadIdx.x;
    if (e >= NE) return;
    int r = blockIdx.y;
    const int* ei = es.e[r];
    int src = __ldg(ei + e);
    int dst = __ldg(ei + NE + e);
    constexpr int D = NV4 * 4;
    const float4* fs = reinterpret_cast<const float4*>(feat + (size_t)src * D);
    float4 v[NV4];
#pragma unroll
    for (int i = 0; i < NV4; i++) v[i] = __ldg(fs + i);
    float* m = msg + ((size_t)r * NN + dst) * D;
#pragma unroll
    for (int i = 0; i < NV4; i++) red_add_v4(m + 4 * i, v[i]);
    float* c = es.cnt[r];
    if (c) atomicAdd(c + dst, 1.0f);
}

// ---------------- node-parallel GEMM: out = act( sum_ch scale_ch(node) * src_ch[node] @ W_ch + bias ) ----------------
template <int CHUNK, int NCH, int OUT, bool RELU>
__global__ void __launch_bounds__(256)
k_gemm(GSrc s, const float* __restrict__ Wcat, const float* __restrict__ bias,
       float* __restrict__ out) {
    __shared__ __align__(16) float shW[CHUNK * OUT];
    __shared__ float shT[256 * (CHUNK + 1)];
    int tid  = threadIdx.x;
    int base = blockIdx.x * 256;
    int node = base + tid;

    float acc[OUT];
#pragma unroll
    for (int j = 0; j < OUT; j++) acc[j] = bias[j];

    for (int ch = 0; ch < NCH; ch++) {
        __syncthreads();
        for (int i = tid; i < CHUNK * OUT; i += 256)
            shW[i] = Wcat[ch * CHUNK * OUT + i];
        const float* src = s.p[ch];
        for (int i = tid; i < 256 * CHUNK; i += 256) {
            int nl = i / CHUNK, k = i - nl * CHUNK;
            int nd = base + nl;
            shT[nl * (CHUNK + 1) + k] = (nd < NN) ? src[(size_t)nd * CHUNK + k] : 0.f;
        }
        __syncthreads();
        float sc = 1.f;
        const float* cp = s.cnt[ch];
        if (cp != nullptr && node < NN) sc = 1.f / fmaxf(cp[node], 1.f);
#pragma unroll 8
        for (int k = 0; k < CHUNK; k++) {
            float m = shT[tid * (CHUNK + 1) + k] * sc;
            const float4* w4 = reinterpret_cast<const float4*>(shW + k * OUT);
#pragma unroll
            for (int j = 0; j < OUT / 4; j++) {
                float4 w = w4[j];
                acc[4 * j + 0] += m * w.x;
                acc[4 * j + 1] += m * w.y;
                acc[4 * j + 2] += m * w.z;
                acc[4 * j + 3] += m * w.w;
            }
        }
    }

    if (node < NN) {
        float4* o4 = reinterpret_cast<float4*>(out + (size_t)node * OUT);
#pragma unroll
        for (int j = 0; j < OUT / 4; j++) {
            float4 v;
            v.x = acc[4 * j + 0]; v.y = acc[4 * j + 1];
            v.z = acc[4 * j + 2]; v.w = acc[4 * j + 3];
            if (RELU) {
                v.x = fmaxf(v.x, 0.f); v.y = fmaxf(v.y, 0.f);
                v.z = fmaxf(v.z, 0.f); v.w = fmaxf(v.w, 0.f);
            }
            o4[j] = v;
        }
    }
}

// ---------------- host ----------------
extern "C" void kernel_launch(void* const* d_in, const int* in_sizes, int n_in,
                              void* d_out, int out_size) {
    (void)n_in; (void)out_size;
    const float* x = (const float*)d_in[0];

    // resolve input ordering: edges-after-x (setup_inputs dict order) vs weights-after-x
    int eb, wb;
    if (in_sizes[1] == 2 * NE) { eb = 1; wb = 10; }
    else                        { wb = 1; eb = 14; }

    const int* E[9];
    for (int i = 0; i < 9; i++) E[i] = (const int*)d_in[eb + i];
    const float* W0n = (const float*)d_in[wb + 0];
    const float* W0r = (const float*)d_in[wb + 1];
    const float* b0  = (const float*)d_in[wb + 2];
    const float* W1n = (const float*)d_in[wb + 3];
    const float* W1r = (const float*)d_in[wb + 4];
    const float* b1  = (const float*)d_in[wb + 5];
    const float* P1  = (const float*)d_in[wb + 6];
    const float* pb1 = (const float*)d_in[wb + 7];
    const float* W2n = (const float*)d_in[wb + 8];
    const float* W2r = (const float*)d_in[wb + 9];
    const float* b2  = (const float*)d_in[wb + 10];
    const float* P2  = (const float*)d_in[wb + 11];
    const float* pb2 = (const float*)d_in[wb + 12];

    float *msg2, *msg1, *msg0, *cnt, *h0, *h1, *Wc0, *Wc1, *Wc2, *bc0, *bc1, *bc2;
    cudaGetSymbolAddress((void**)&msg2, g_msg2);
    cudaGetSymbolAddress((void**)&msg1, g_msg1);
    cudaGetSymbolAddress((void**)&msg0, g_msg0);
    cudaGetSymbolAddress((void**)&cnt,  g_cnt);
    cudaGetSymbolAddress((void**)&h0,   g_h0);
    cudaGetSymbolAddress((void**)&h1,   g_h1);
    cudaGetSymbolAddress((void**)&Wc0,  g_Wc0);
    cudaGetSymbolAddress((void**)&Wc1,  g_Wc1);
    cudaGetSymbolAddress((void**)&Wc2,  g_Wc2);
    cudaGetSymbolAddress((void**)&bc0,  g_bc0);
    cudaGetSymbolAddress((void**)&bc1,  g_bc1);
    cudaGetSymbolAddress((void**)&bc2,  g_bc2);

    k_zero<<<2048, 256>>>();
    k_prep<<<56, 256>>>(W0n, W0r, b0, W1n, W1r, b1, P1, pb1, W2n, W2r, b2, P2, pb2);

    // ---- layer 0: x(6) -> h0(16), relations {connected_to, ordered_next}, sum ----
    ESet es01 = {};
    es01.e[0] = E[0]; es01.e[1] = E[1];
    k_scatter6<<<dim3(NE / 256, 2), 256>>>(es01, x, msg0);

    GSrc s0 = {};
    s0.p[0] = msg0; s0.p[1] = msg0 + (size_t)NN * 6; s0.p[2] = x;
    k_gemm<6, 3, 16, false><<<(NN + 255) / 256, 256>>>(s0, Wc0, bc0, h0);

    // ---- layer 1: h0(16) -> h1(32), same relations, + P1 residual, relu ----
    k_scatter<4><<<dim3(NE / 256, 2), 256>>>(es01, h0, msg1);

    GSrc s1 = {};
    s1.p[0] = msg1; s1.p[1] = msg1 + (size_t)NN * 16; s1.p[2] = h0;
    k_gemm<16, 3, 32, true><<<(NN + 255) / 256, 256>>>(s1, Wc1, bc1, h1);

    // ---- layer 2: h1(32) -> out(64), 7 relations (mean at 2,3,6), + P2, relu ----
    ESet es2 = {};
    for (int r = 0; r < 7; r++) es2.e[r] = E[2 + r];
    es2.cnt[2] = cnt; es2.cnt[3] = cnt + NN; es2.cnt[6] = cnt + 2 * NN;
    k_scatter<8><<<dim3(NE / 256, 7), 256>>>(es2, h1, msg2);

    GSrc s2 = {};
    for (int r = 0; r < 7; r++) s2.p[r] = msg2 + (size_t)r * NN * 32;
    s2.p[7] = h1;
    s2.cnt[2] = cnt; s2.cnt[3] = cnt + NN; s2.cnt[6] = cnt + 2 * NN;
    k_gemm<32, 8, 64, true><<<(NN + 255) / 256, 256>>>(s2, Wc2, bc2, (float*)d_out);
}